// round 14
// baseline (speedup 1.0000x reference)
#include <cuda_runtime.h>

#define B_  2
#define H_  12
#define S_  2048
#define D_  64
#define BR  128
#define BC  64
#define NT  256
#define KST 72                          // bf16 row stride (144B)
#define NITEMS ((S_ / BR) * H_ * B_)    // 384
#define NCTAS  296

typedef unsigned int u32;

__device__ int g_seg_start[B_ * S_];
__device__ u32 g_ctr;

__global__ void segstart_kernel(const int* __restrict__ block_ids) {
    int idx = blockIdx.x * blockDim.x + threadIdx.x;
    if (idx == 0) g_ctr = 0u;
    if (idx >= B_ * S_) return;
    int b = idx / S_, qpos = idx % S_;
    const int* bi = block_ids + b * S_;
    int val = bi[qpos];
    int lo = 0, hi = qpos;
    while (lo < hi) {
        int mid = (lo + hi) >> 1;
        if (bi[mid] < val) lo = mid + 1; else hi = mid;
    }
    g_seg_start[idx] = lo;
}

__device__ __forceinline__ u32 smem_u32(const void* p) {
    u32 a;
    asm("{ .reg .u64 t; cvta.to.shared.u64 t, %1; cvt.u32.u64 %0, t; }"
        : "=r"(a) : "l"(p));
    return a;
}
__device__ __forceinline__ float ex2f(float x) {
    float y; asm("ex2.approx.ftz.f32 %0, %1;" : "=f"(y) : "f"(x)); return y;
}
__device__ __forceinline__ void bsplit(float e, float o, u32& hi, u32& lo) {
    asm("cvt.rn.bf16x2.f32 %0, %1, %2;" : "=r"(hi) : "f"(o), "f"(e));
    float eh = __uint_as_float(hi << 16);
    float oh = __uint_as_float(hi & 0xFFFF0000u);
    asm("cvt.rn.bf16x2.f32 %0, %1, %2;" : "=r"(lo) : "f"(o - oh), "f"(e - eh));
}
__device__ __forceinline__ void ldsm4(u32* r, u32 a) {
    asm volatile("ldmatrix.sync.aligned.m8n8.x4.shared.b16 {%0,%1,%2,%3}, [%4];"
                 : "=r"(r[0]), "=r"(r[1]), "=r"(r[2]), "=r"(r[3]) : "r"(a));
}
__device__ __forceinline__ void ldsm4t(u32* r, u32 a) {
    asm volatile("ldmatrix.sync.aligned.m8n8.x4.trans.shared.b16 {%0,%1,%2,%3}, [%4];"
                 : "=r"(r[0]), "=r"(r[1]), "=r"(r[2]), "=r"(r[3]) : "r"(a));
}
__device__ __forceinline__ void mma16816(float* d, const u32* a, u32 b0, u32 b1) {
    asm volatile(
        "mma.sync.aligned.m16n8k16.row.col.f32.bf16.bf16.f32 "
        "{%0,%1,%2,%3},{%4,%5,%6,%7},{%8,%9},{%0,%1,%2,%3};"
        : "+f"(d[0]), "+f"(d[1]), "+f"(d[2]), "+f"(d[3])
        : "r"(a[0]), "r"(a[1]), "r"(a[2]), "r"(a[3]), "r"(b0), "r"(b1));
}
#define STS128(addr, r0, r1, r2, r3) \
    asm volatile("st.shared.v4.b32 [%0], {%1,%2,%3,%4};" :: \
        "r"(addr), "r"(r0), "r"(r1), "r"(r2), "r"(r3))

// convert one K/V tile (64 keys x 64 dims fp32) -> bf16 hi/lo, stride KST
__device__ __forceinline__ void convert_kv(
    const float* __restrict__ Kb, const float* __restrict__ Vb, int kt,
    u32 KH, u32 KL, u32 VH, u32 VL, int ckey, int cdg) {
    const float4* ks4 = (const float4*)&Kb[(long)(kt + ckey) * D_ + cdg];
    const float4* vs4 = (const float4*)&Vb[(long)(kt + ckey) * D_ + cdg];
    u32 off = (u32)((ckey * KST + cdg) * 2);
    u32 h8[8], l8[8];
    #pragma unroll
    for (int i = 0; i < 4; i++) {
        float4 f = ks4[i];
        bsplit(f.x, f.y, h8[2*i], l8[2*i]);
        bsplit(f.z, f.w, h8[2*i+1], l8[2*i+1]);
    }
    STS128(KH + off,      h8[0], h8[1], h8[2], h8[3]);
    STS128(KH + off + 16, h8[4], h8[5], h8[6], h8[7]);
    STS128(KL + off,      l8[0], l8[1], l8[2], l8[3]);
    STS128(KL + off + 16, l8[4], l8[5], l8[6], l8[7]);
    #pragma unroll
    for (int i = 0; i < 4; i++) {
        float4 f = vs4[i];
        bsplit(f.x, f.y, h8[2*i], l8[2*i]);
        bsplit(f.z, f.w, h8[2*i+1], l8[2*i+1]);
    }
    STS128(VH + off,      h8[0], h8[1], h8[2], h8[3]);
    STS128(VH + off + 16, h8[4], h8[5], h8[6], h8[7]);
    STS128(VL + off,      l8[0], l8[1], l8[2], l8[3]);
    STS128(VL + off + 16, l8[4], l8[5], l8[6], l8[7]);
}

extern __shared__ char dsm[];

__global__ __launch_bounds__(NT, 2)
void attn_kernel(const float* __restrict__ Q, const float* __restrict__ K,
                 const float* __restrict__ V, float* __restrict__ O) {
    __shared__ int s_item;
    const u32 base = smem_u32(dsm);
    const u32 QH = base, QL = base + 18432;
    // double-buffered converted K/V: each buf = KH,KL,VH,VL x 9216B
    const u32 kvb[2] = { base + 36864, base + 73728 };

    const int t = threadIdx.x;
    const int w = t >> 5, lane = t & 31;
    const int g = lane >> 2, qd = lane & 3;

    const int ckey = t >> 2, cdg = (t & 3) * 16;      // K/V convert slice
    const int qr = t >> 1, qhh = (t & 1) * 32;        // Q convert slice

    const u32 a_off = (u32)(((lane & 15) * KST + 8 * (lane >> 4)) * 2);
    const u32 bk_off = (u32)((((lane & 7) + ((lane >= 16) ? 8 : 0)) * KST
                              + 8 * ((lane >> 3) & 1)) * 2);
    const u32 v_off = (u32)((((lane & 7) + 8 * ((lane >> 3) & 1)) * KST
                             + ((lane >= 16) ? 8 : 0)) * 2);
    const u32 arow_off = (u32)(16 * w * KST * 2);

    const float QSCALE = 0.125f * 1.44269504088896340736f;

    for (;;) {
        if (t == 0) s_item = (int)atomicAdd(&g_ctr, 1u);
        __syncthreads();
        const int wk = s_item;
        if (wk >= NITEMS) return;

        const int qt = (S_ / BR - 1) - wk / (B_ * H_);   // heavy-first
        const int hb = wk % (B_ * H_);
        const int h = hb % H_, b = hb / H_;
        const int q0 = qt * BR;
        const long gbase = ((long)(b * H_ + h)) * S_ * D_;
        const float* Qb = Q + gbase + (long)q0 * D_;
        const float* Kb = K + gbase;
        const float* Vb = V + gbase;

        const int kstart = (g_seg_start[b * S_ + q0] / BC) * BC;
        const int klast = q0 + 64;

        // ---- Q convert: prescale, split, store bf16 hi/lo ----
        {
            const float4* src = (const float4*)&Qb[qr * D_ + qhh];
            u32 hh[16], ll[16];
            #pragma unroll
            for (int i = 0; i < 8; i++) {
                float4 f = src[i];
                f.x *= QSCALE; f.y *= QSCALE; f.z *= QSCALE; f.w *= QSCALE;
                bsplit(f.x, f.y, hh[2 * i], ll[2 * i]);
                bsplit(f.z, f.w, hh[2 * i + 1], ll[2 * i + 1]);
            }
            u32 off = (u32)((qr * KST + qhh) * 2);
            #pragma unroll
            for (int i = 0; i < 4; i++) {
                STS128(QH + off + 16 * i, hh[4*i], hh[4*i+1], hh[4*i+2], hh[4*i+3]);
                STS128(QL + off + 16 * i, ll[4*i], ll[4*i+1], ll[4*i+2], ll[4*i+3]);
            }
        }
        // prologue: convert first K/V tile into buf 0
        convert_kv(Kb, Vb, kstart, kvb[0], kvb[0] + 9216,
                   kvb[0] + 18432, kvb[0] + 27648, ckey, cdg);
        __syncthreads();

        const int rg0 = q0 + 16 * w + g, rg1 = rg0 + 8;
        const int st0 = g_seg_start[b * S_ + rg0];
        const int st1 = g_seg_start[b * S_ + rg1];

        float Oa[32];
        #pragma unroll
        for (int i = 0; i < 32; i++) Oa[i] = 0.f;
        float l0 = 0.f, l1 = 0.f;

        int buf = 0;
        for (int kt = kstart; kt <= klast; kt += BC, buf ^= 1) {
            const u32 KH = kvb[buf], KL = KH + 9216;
            const u32 VH = KH + 18432, VL = KH + 27648;

            // convert NEXT tile into buf^1 (overlaps this tile's MMAs;
            // buf^1's previous readers finished before the last barrier)
            if (kt + BC <= klast) {
                const u32 nKH = kvb[buf ^ 1];
                convert_kv(Kb, Vb, kt + BC, nKH, nKH + 9216,
                           nKH + 18432, nKH + 27648, ckey, cdg);
            }

            // ---- QK: S = Qh*Kh + Qh*Kl + Ql*Kh (fp32 accum) ----
            float Sa[32];
            #pragma unroll
            for (int i = 0; i < 32; i++) Sa[i] = 0.f;
            u32 ah[16];
            #pragma unroll
            for (int ks = 0; ks < 4; ks++)
                ldsm4(&ah[4 * ks], QH + arow_off + a_off + 32 * ks);
            #pragma unroll
            for (int ks = 0; ks < 4; ks++) {
                #pragma unroll
                for (int jp = 0; jp < 4; jp++) {
                    u32 bh[4], bl[4];
                    ldsm4(bh, KH + bk_off + (u32)(jp * 2304 + ks * 32));
                    ldsm4(bl, KL + bk_off + (u32)(jp * 2304 + ks * 32));
                    mma16816(&Sa[8 * jp],     &ah[4 * ks], bh[0], bh[1]);
                    mma16816(&Sa[8 * jp + 4], &ah[4 * ks], bh[2], bh[3]);
                    mma16816(&Sa[8 * jp],     &ah[4 * ks], bl[0], bl[1]);
                    mma16816(&Sa[8 * jp + 4], &ah[4 * ks], bl[2], bl[3]);
                }
            }
            #pragma unroll
            for (int ks = 0; ks < 4; ks++)
                ldsm4(&ah[4 * ks], QL + arow_off + a_off + 32 * ks);
            #pragma unroll
            for (int ks = 0; ks < 4; ks++) {
                #pragma unroll
                for (int jp = 0; jp < 4; jp++) {
                    u32 bh[4];
                    ldsm4(bh, KH + bk_off + (u32)(jp * 2304 + ks * 32));
                    mma16816(&Sa[8 * jp],     &ah[4 * ks], bh[0], bh[1]);
                    mma16816(&Sa[8 * jp + 4], &ah[4 * ks], bh[2], bh[3]);
                }
            }

            // ---- mask + exp2 (unstable ghost-softmax) -> P A-frags ----
            u32 ph[16], pl[16];
            float la0 = 0.f, la1 = 0.f;
            #pragma unroll
            for (int j = 0; j < 8; j++) {
                const float* s4 = &Sa[4 * j];
                int c0 = kt + 8 * j + 2 * qd, c1 = c0 + 1;
                float p0 = (c0 >= st0 && c0 <= rg0) ? ex2f(s4[0]) : 0.f;
                float p1 = (c1 >= st0 && c1 <= rg0) ? ex2f(s4[1]) : 0.f;
                float p2 = (c0 >= st1 && c0 <= rg1) ? ex2f(s4[2]) : 0.f;
                float p3 = (c1 >= st1 && c1 <= rg1) ? ex2f(s4[3]) : 0.f;
                la0 += p0 + p1; la1 += p2 + p3;
                int idx = 4 * (j >> 1) + 2 * (j & 1);
                bsplit(p0, p1, ph[idx],     pl[idx]);
                bsplit(p2, p3, ph[idx + 1], pl[idx + 1]);
            }
            l0 += la0; l1 += la1;

            // ---- PV: O += Ph*Vh + Ph*Vl + Pl*Vh ----
            #pragma unroll
            for (int ks = 0; ks < 4; ks++) {
                #pragma unroll
                for (int jp = 0; jp < 4; jp++) {
                    u32 bh[4], bl[4];
                    ldsm4t(bh, VH + v_off + (u32)(ks * 2304 + jp * 32));
                    ldsm4t(bl, VL + v_off + (u32)(ks * 2304 + jp * 32));
                    mma16816(&Oa[8 * jp],     &ph[4 * ks], bh[0], bh[1]);
                    mma16816(&Oa[8 * jp + 4], &ph[4 * ks], bh[2], bh[3]);
                    mma16816(&Oa[8 * jp],     &ph[4 * ks], bl[0], bl[1]);
                    mma16816(&Oa[8 * jp + 4], &ph[4 * ks], bl[2], bl[3]);
                    mma16816(&Oa[8 * jp],     &pl[4 * ks], bh[0], bh[1]);
                    mma16816(&Oa[8 * jp + 4], &pl[4 * ks], bh[2], bh[3]);
                }
            }
            __syncthreads();   // tile done: MMA reads of buf + converts to buf^1
        }

        // ---- epilogue: quad reduce l, normalize (ghost +1), store ----
        l0 += __shfl_xor_sync(0xffffffffu, l0, 1);
        l0 += __shfl_xor_sync(0xffffffffu, l0, 2);
        l1 += __shfl_xor_sync(0xffffffffu, l1, 1);
        l1 += __shfl_xor_sync(0xffffffffu, l1, 2);
        float inv0 = 1.f / (1.f + l0), inv1 = 1.f / (1.f + l1);
        float* Ob = (float*)O + gbase;
        #pragma unroll
        for (int j = 0; j < 8; j++) {
            int dc = 8 * j + 2 * qd;
            *(float2*)&Ob[(long)rg0 * D_ + dc] =
                make_float2(Oa[4 * j] * inv0, Oa[4 * j + 1] * inv0);
            *(float2*)&Ob[(long)rg1 * D_ + dc] =
                make_float2(Oa[4 * j + 2] * inv1, Oa[4 * j + 3] * inv1);
        }
    }
}

extern "C" void kernel_launch(void* const* d_in, const int* in_sizes, int n_in,
                              void* d_out, int out_size) {
    const float* q  = (const float*)d_in[0];
    const float* k  = (const float*)d_in[1];
    const float* v  = (const float*)d_in[2];
    const int* bids = (const int*)d_in[3];
    float* out      = (float*)d_out;

    segstart_kernel<<<(B_ * S_ + 255) / 256, 256>>>(bids);

    // Q 36864 + 2 x KV 36864 = 110592 bytes (2 CTAs/SM: 221184 < 228KB)
    const int smem_bytes = 110592;
    cudaFuncSetAttribute(attn_kernel, cudaFuncAttributeMaxDynamicSharedMemorySize,
                         smem_bytes);
    attn_kernel<<<NCTAS, NT, smem_bytes>>>(q, k, v, out);
}